// round 4
// baseline (speedup 1.0000x reference)
#include <cuda_runtime.h>
#include <cstdint>

#define SDIM 128
#define S3 (SDIM*SDIM*SDIM)
#define NBATCH 2
#define NPTS 250000
#define MTOT (NBATCH*NPTS)
#define CCH 32
#define NK 27

typedef unsigned long long ull;

// ---- static device scratch ----
__device__ int   g_grid [NBATCH*S3];         // 16.8 MB dense voxel grid
__device__ int   g_kcnt [NK];                // pairs per kernel offset
__device__ int   g_scnt [MTOT];              // slots (valid taps) per point
__device__ int2  g_pairs[NK*MTOT];           // 108 MB: per-k pair lists {in_idx, (p<<5)|slot}
__device__ float g_tmp  [(size_t)NK*MTOT*CCH]; // 1.73 GB partials, (p,slot) slot-dense
__device__ float g_buf1 [MTOT*CCH];
__device__ float g_buf2 [MTOT*CCH];

// ---- f32x2 packed helpers (PTX 8.6, sm_100+) ----
__device__ __forceinline__ ull pack2(float x, float y){
    ull r; asm("mov.b64 %0, {%1,%2};" : "=l"(r)
               : "r"(__float_as_uint(x)), "r"(__float_as_uint(y))); return r;
}
__device__ __forceinline__ void unpack2(ull v, float& x, float& y){
    unsigned lo, hi; asm("mov.b64 {%0,%1}, %2;" : "=r"(lo), "=r"(hi) : "l"(v));
    x = __uint_as_float(lo); y = __uint_as_float(hi);
}
__device__ __forceinline__ ull fma2(ull a, ull b, ull c){
    ull d; asm("fma.rn.f32x2 %0, %1, %2, %3;" : "=l"(d) : "l"(a), "l"(b), "l"(c)); return d;
}
__device__ __forceinline__ ull add2(ull a, ull b){
    ull d; asm("add.rn.f32x2 %0, %1, %2;" : "=l"(d) : "l"(a), "l"(b)); return d;
}

// ---------------------------------------------------------------
__global__ void clear_grid_kernel() {
    int i = blockIdx.x*blockDim.x + threadIdx.x;   // 4096*256 == S3*NBATCH/4
    ((int4*)g_grid)[i] = make_int4(-1,-1,-1,-1);
    if (blockIdx.x == 0 && threadIdx.x < NK) g_kcnt[threadIdx.x] = 0;
}

__global__ void scatter_kernel(const int* __restrict__ coords) {
    int p = blockIdx.x*blockDim.x + threadIdx.x;
    if (p >= MTOT) return;
    int cx = coords[3*p], cy = coords[3*p+1], cz = coords[3*p+2];
    g_grid[(p/NPTS)*S3 + (cx*SDIM + cy)*SDIM + cz] = p;
}

__global__ void build_kernel(const int* __restrict__ coords) {
    int p = blockIdx.x*blockDim.x + threadIdx.x;
    const bool pv = (p < MTOT);
    int cx = 0, cy = 0, cz = 0;
    if (pv) { cx = coords[3*p]; cy = coords[3*p+1]; cz = coords[3*p+2]; }
    const int* gb = g_grid + (pv ? (p/NPTS)*S3 : 0);

    unsigned mask = 0;
    int nidx[NK];
    if (pv) {
        #pragma unroll
        for (int dx = 0; dx < 3; dx++) {
            int nx = cx + dx - 1;
            if ((unsigned)nx >= SDIM) continue;
            #pragma unroll
            for (int dy = 0; dy < 3; dy++) {
                int ny = cy + dy - 1;
                if ((unsigned)ny >= SDIM) continue;
                int base = (nx*SDIM + ny)*SDIM;
                #pragma unroll
                for (int dz = 0; dz < 3; dz++) {
                    int nz = cz + dz - 1;
                    if ((unsigned)nz >= SDIM) continue;
                    int idx = gb[base + nz];
                    if (idx >= 0) {
                        int k = (dx*3 + dy)*3 + dz;
                        mask |= (1u << k);
                        nidx[k] = idx;
                    }
                }
            }
        }
        g_scnt[p] = __popc(mask);
    }

    unsigned lt; asm("mov.u32 %0, %%lanemask_lt;" : "=r"(lt));
    // warp-aggregated emission: 1 atomic per warp per present k
    #pragma unroll
    for (int k = 0; k < NK; k++) {
        unsigned bal = __ballot_sync(0xFFFFFFFFu, (mask >> k) & 1u);
        if (!bal) continue;
        int nk  = __popc(bal);
        int ldr = __ffs(bal) - 1;
        int basepos = 0;
        if ((int)(threadIdx.x & 31) == ldr) basepos = atomicAdd(&g_kcnt[k], nk);
        basepos = __shfl_sync(0xFFFFFFFFu, basepos, ldr);
        if ((mask >> k) & 1u) {
            int pos  = basepos + __popc(bal & lt);
            int slot = __popc(mask & ((1u << k) - 1u));
            g_pairs[k*MTOT + pos] = make_int2(nidx[k], (p << 5) | slot);
        }
    }
}

// ---------------------------------------------------------------
// Phase 1: per-k pair GEMV, 2 pairs per warp-step via packed f32x2.
#define P1_THREADS 256
#define P1_WARPS   8
#define PPW        128     // pairs per warp

__global__ void __launch_bounds__(P1_THREADS, 2)
conv_pairs_kernel(const float* __restrict__ fext_in, const float* __restrict__ Wg,
                  int in_mode)
{
    __shared__ __align__(16) float2 sAB[P1_WARPS][2][CCH];   // interleaved (fA[j], fB[j]), double-buffered
    const int k    = blockIdx.y;
    const int cnt  = g_kcnt[k];
    const int warp = threadIdx.x >> 5, lane = threadIdx.x & 31;
    const int half = lane >> 4,        hl   = lane & 15;
    const int base0 = (blockIdx.x*P1_WARPS + warp)*PPW;
    if (base0 >= cnt) return;

    const float* fin = (in_mode == 0) ? fext_in : (in_mode == 1 ? g_buf1 : g_buf2);

    // W[k] dup-packed into registers: wd[j] = (W[j][c], W[j][c]), c = lane
    ull wd[CCH];
    #pragma unroll
    for (int j = 0; j < CCH; j++) {
        float w = Wg[k*CCH*CCH + j*CCH + lane];
        wd[j] = pack2(w, w);
    }

    const int2* plist = g_pairs + k*MTOT;

    for (int b = 0; b < PPW/32; b++) {
        const int gbase = base0 + b*32;
        if (gbase >= cnt) break;
        int nval = cnt - gbase; if (nval > 32) nval = 32;

        int2 pd = make_int2(0, 0);
        if (gbase + lane < cnt) pd = plist[gbase + lane];

        // prologue: gather row for step e=0 (half 0 -> pair 0, half 1 -> pair 1)
        int ix = __shfl_sync(0xFFFFFFFFu, pd.x, half);
        float2 f2 = *(const float2*)(fin + (size_t)ix*CCH + hl*2);

        for (int e = 0; 2*e < nval; e++) {
            const int dA = __shfl_sync(0xFFFFFFFFu, pd.y, 2*e);
            const int dB = __shfl_sync(0xFFFFFFFFu, pd.y, (2*e + 1) & 31);

            // prefetch next step's rows
            float2 nf2 = f2;
            int nix = __shfl_sync(0xFFFFFFFFu, pd.x, (2*e + 2 + half) & 31);
            if (2*e + 2 < nval)
                nf2 = *(const float2*)(fin + (size_t)nix*CCH + hl*2);

            // stage interleaved (fA[j], fB[j])
            float2* sb = &sAB[warp][e & 1][0];
            if (half == 0) { sb[2*hl].x = f2.x; sb[2*hl + 1].x = f2.y; }
            else           { sb[2*hl].y = f2.x; sb[2*hl + 1].y = f2.y; }
            __syncwarp();

            ull a0 = 0, a1 = 0, a2 = 0, a3 = 0;
            #pragma unroll
            for (int t = 0; t < 16; t++) {
                ulonglong2 vv = *(const ulonglong2*)&sb[2*t];   // LDS.128 broadcast
                if (t & 1) { a2 = fma2(vv.x, wd[2*t], a2); a3 = fma2(vv.y, wd[2*t+1], a3); }
                else       { a0 = fma2(vv.x, wd[2*t], a0); a1 = fma2(vv.y, wd[2*t+1], a1); }
            }
            ull s = add2(add2(a0, a2), add2(a1, a3));
            float va, vb; unpack2(s, va, vb);

            g_tmp[(size_t)((dA >> 5)*NK + (dA & 31))*CCH + lane] = va;
            if (2*e + 1 < nval)
                g_tmp[(size_t)((dB >> 5)*NK + (dB & 31))*CCH + lane] = vb;

            f2 = nf2;
        }
    }
}

// ---------------------------------------------------------------
// Phase 2: per-point streaming sum over slot-dense partial rows + fused ReLU.
template<bool RELU>
__global__ void __launch_bounds__(256)
reduce_kernel(float* __restrict__ fext_out, int out_mode)
{
    const int p = blockIdx.x*8 + (threadIdx.x >> 5);
    if (p >= MTOT) return;
    const int lane = threadIdx.x & 31;
    float* fout = (out_mode == 0) ? fext_out : (out_mode == 1 ? g_buf1 : g_buf2);

    const int c = g_scnt[p];
    const float* t = g_tmp + (size_t)p*NK*CCH + lane;
    float a0 = 0.f, a1 = 0.f, a2 = 0.f, a3 = 0.f;
    int s = 0;
    for (; s + 4 <= c; s += 4) {     // 4-deep MLP
        a0 += t[(s  )*CCH]; a1 += t[(s+1)*CCH];
        a2 += t[(s+2)*CCH]; a3 += t[(s+3)*CCH];
    }
    for (; s < c; s++) a0 += t[s*CCH];
    float r = (a0 + a1) + (a2 + a3);
    if (RELU) r = fmaxf(r, 0.f);
    fout[(size_t)p*CCH + lane] = r;
}

// ---------------------------------------------------------------
extern "C" void kernel_launch(void* const* d_in, const int* in_sizes, int n_in,
                              void* d_out, int out_size)
{
    const float* features = (const float*)d_in[0];
    const int*   coords   = (const int*)  d_in[1];
    const float* W1 = (const float*)d_in[n_in-3];
    const float* W2 = (const float*)d_in[n_in-2];
    const float* W3 = (const float*)d_in[n_in-1];
    float* out = (float*)d_out;

    clear_grid_kernel<<<(NBATCH*S3/4)/256, 256>>>();
    scatter_kernel  <<<(MTOT+255)/256, 256>>>(coords);
    build_kernel    <<<(MTOT+255)/256, 256>>>(coords);

    dim3 g1((MTOT + P1_WARPS*PPW - 1)/(P1_WARPS*PPW), NK);   // (489, 27)
    const int g2 = MTOT/8;                                    // 62500

    conv_pairs_kernel<<<g1, P1_THREADS>>>(features, W1, 0);
    reduce_kernel<true ><<<g2, 256>>>(nullptr, 1);

    conv_pairs_kernel<<<g1, P1_THREADS>>>(nullptr, W2, 1);
    reduce_kernel<true ><<<g2, 256>>>(nullptr, 2);

    conv_pairs_kernel<<<g1, P1_THREADS>>>(nullptr, W3, 2);
    reduce_kernel<false><<<g2, 256>>>(out, 0);
}